// round 16
// baseline (speedup 1.0000x reference)
#include <cuda_runtime.h>
#include <cuda_fp16.h>
#include <cstddef>
#include <cstdint>

#define EDIM   768
#define BATCH  8
#define SEQ    1024
#define NH     12
#define HD     64
#define MTOT   (BATCH * SEQ)   // 8192

// Scratch (no cudaMalloc allowed) — fp16 dataflow.
__device__ __half g_Xh [(size_t)MTOT * EDIM];
__device__ __half g_Wqh[(size_t)EDIM * EDIM];
__device__ __half g_Wkh[(size_t)EDIM * EDIM];
__device__ __half g_Woh[(size_t)EDIM * EDIM];
__device__ __half g_Qh [(size_t)MTOT * EDIM];   // (x@Wq^T + bq) * 0.125*log2(e), fp16
__device__ __half g_Kh [(size_t)MTOT * EDIM];   // x@Wk^T + bk, fp16
__device__ __half g_Oh [(size_t)MTOT * EDIM];   // attention output, fp16

// ---------------------------------------------------------------------------
// helpers
// ---------------------------------------------------------------------------
__device__ __forceinline__ void mma_f16(float* d, const uint32_t* a, const uint32_t* b)
{
    asm volatile(
        "mma.sync.aligned.m16n8k16.row.col.f32.f16.f16.f32 "
        "{%0,%1,%2,%3}, {%4,%5,%6,%7}, {%8,%9}, {%0,%1,%2,%3};\n"
        : "+f"(d[0]), "+f"(d[1]), "+f"(d[2]), "+f"(d[3])
        : "r"(a[0]), "r"(a[1]), "r"(a[2]), "r"(a[3]),
          "r"(b[0]), "r"(b[1]));
}

__device__ __forceinline__ void ldsm4(uint32_t* r, uint32_t saddr)
{
    asm volatile(
        "ldmatrix.sync.aligned.m8n8.x4.shared.b16 {%0,%1,%2,%3}, [%4];\n"
        : "=r"(r[0]), "=r"(r[1]), "=r"(r[2]), "=r"(r[3]) : "r"(saddr));
}

__device__ __forceinline__ void ldsm4t(uint32_t* r, uint32_t saddr)
{
    asm volatile(
        "ldmatrix.sync.aligned.m8n8.x4.trans.shared.b16 {%0,%1,%2,%3}, [%4];\n"
        : "=r"(r[0]), "=r"(r[1]), "=r"(r[2]), "=r"(r[3]) : "r"(saddr));
}

__device__ __forceinline__ uint32_t sptr(const void* p)
{
    return (uint32_t)__cvta_generic_to_shared(p);
}

__device__ __forceinline__ void cp16(uint32_t s, const void* g)
{
    asm volatile("cp.async.cg.shared.global [%0], [%1], 16;\n" :: "r"(s), "l"(g));
}

__device__ __forceinline__ uint32_t h2u(float a, float b)
{
    __half2 h = __floats2half2_rn(a, b);
    return *reinterpret_cast<uint32_t*>(&h);
}

__device__ __forceinline__ float ex2(float x)
{
    float r;
    asm("ex2.approx.f32 %0, %1;" : "=f"(r) : "f"(x));
    return r;
}

// Convert x, Wq, Wk, Wo to fp16 in one launch (8 floats per thread).
__global__ void cvt_half_kernel(
    const float* __restrict__ x,  const float* __restrict__ wq,
    const float* __restrict__ wk, const float* __restrict__ wo,
    __half* __restrict__ xo, __half* __restrict__ wqo,
    __half* __restrict__ wko, __half* __restrict__ woo)
{
    const int NX8 = MTOT * EDIM / 8;
    const int NW8 = EDIM * EDIM / 8;
    int i = blockIdx.x * blockDim.x + threadIdx.x;
    const float4* src; uint4* dst; int j;
    if (i < NX8)                { src = (const float4*)x;  dst = (uint4*)xo;  j = i; }
    else if (i < NX8 + NW8)     { src = (const float4*)wq; dst = (uint4*)wqo; j = i - NX8; }
    else if (i < NX8 + 2 * NW8) { src = (const float4*)wk; dst = (uint4*)wko; j = i - NX8 - NW8; }
    else if (i < NX8 + 3 * NW8) { src = (const float4*)wo; dst = (uint4*)woo; j = i - NX8 - 2 * NW8; }
    else return;
    float4 v0 = src[2 * j], v1 = src[2 * j + 1];
    uint4 pk;
    pk.x = h2u(v0.x, v0.y); pk.y = h2u(v0.z, v0.w);
    pk.z = h2u(v1.x, v1.y); pk.w = h2u(v1.z, v1.w);
    dst[j] = pk;
}

// ---------------------------------------------------------------------------
// GEMM (NT) fp16 m16n8k16, CTA 128x128 (for fused QK projections).
// 4-stage cp.async ring + LDSM; fp32 accum. blockIdx.z selects output set.
// ---------------------------------------------------------------------------
#define BM 128
#define BN 128
#define BKH 32
#define SPH 40
#define NSTG 4
#define STG_HALVES (2 * 128 * SPH)
#define STG_BYTES  (STG_HALVES * 2)
#define GEMM_SMEM_BYTES (NSTG * STG_BYTES)

__device__ __forceinline__ void gemm_load_stage_h(
    uint32_t sa, uint32_t sw, const __half* A, const __half* W,
    int m0, int n0, int k0, int K, int tid)
{
    const int r  = tid >> 1;
    const int g0 = (tid & 1) * 2;
#pragma unroll
    for (int j = 0; j < 2; j++) {
        const int gg = g0 + j;
        const uint32_t soff = (uint32_t)((r * SPH + gg * 8) * 2);
        cp16(sa + soff, &A[(size_t)(m0 + r) * K + k0 + gg * 8]);
        cp16(sw + soff, &W[(size_t)(n0 + r) * K + k0 + gg * 8]);
    }
}

__global__ __launch_bounds__(256, 2) void gemm_f16_bias(
    const __half* __restrict__ A,
    const __half* __restrict__ W0, const __half* __restrict__ W1,
    const float* __restrict__ b0, const float* __restrict__ b1,
    __half* __restrict__ C0, __half* __restrict__ C1,
    int M, int N, int K, float s0, float s1)
{
    const __half* W    = blockIdx.z ? W1 : W0;
    const float*  bias = blockIdx.z ? b1 : b0;
    __half*       Cout = blockIdx.z ? C1 : C0;
    const float  scale = blockIdx.z ? s1 : s0;

    extern __shared__ __half smh[];
    const uint32_t base = sptr(smh);

    const int tid  = threadIdx.x;
    const int warp = tid >> 5;
    const int lane = tid & 31;
    const int g    = lane >> 2;
    const int t    = lane & 3;

    const int wm = (warp & 1) * 64;
    const int wn = (warp >> 1) * 32;
    const int m0 = blockIdx.y * BM;
    const int n0 = blockIdx.x * BN;

    const int frow = (lane & 7) + ((lane >> 3) & 1) * 8;
    const int fcol = (lane >> 4) * 8;
    uint32_t aab[4], bab[2];
#pragma unroll
    for (int mt = 0; mt < 4; mt++)
        aab[mt] = base + (uint32_t)(((wm + mt * 16 + frow) * SPH + fcol) * 2);
#pragma unroll
    for (int j = 0; j < 2; j++)
        bab[j] = base + (uint32_t)((128 * SPH + (wn + j * 16 + frow) * SPH + fcol) * 2);

    float acc[4][4][4];
#pragma unroll
    for (int i = 0; i < 4; i++)
#pragma unroll
        for (int j = 0; j < 4; j++)
#pragma unroll
            for (int c = 0; c < 4; c++) acc[i][j][c] = 0.0f;

    const int NIT = K / BKH;   // 24

#pragma unroll
    for (int s = 0; s < NSTG - 1; s++) {
        gemm_load_stage_h(base + s * STG_BYTES, base + s * STG_BYTES + 128 * SPH * 2,
                          A, W, m0, n0, s * BKH, K, tid);
        asm volatile("cp.async.commit_group;\n");
    }

    for (int it = 0; it < NIT; it++) {
        asm volatile("cp.async.wait_group %0;\n" :: "n"(NSTG - 2));
        __syncthreads();

        {
            const int ld = it + NSTG - 1;
            if (ld < NIT) {
                const uint32_t so = (uint32_t)((ld % NSTG) * STG_BYTES);
                gemm_load_stage_h(base + so, base + so + 128 * SPH * 2,
                                  A, W, m0, n0, ld * BKH, K, tid);
            }
            asm volatile("cp.async.commit_group;\n");
        }

        const uint32_t soff = (uint32_t)((it % NSTG) * STG_BYTES);

#pragma unroll
        for (int kc = 0; kc < 2; kc++) {
            const uint32_t koff = soff + kc * 32;
            uint32_t a[4][4], b[2][4];
#pragma unroll
            for (int mt = 0; mt < 4; mt++) ldsm4(a[mt], aab[mt] + koff);
#pragma unroll
            for (int j = 0; j < 2; j++)    ldsm4(b[j],  bab[j] + koff);
#pragma unroll
            for (int mt = 0; mt < 4; mt++)
#pragma unroll
                for (int nt = 0; nt < 4; nt++) {
                    uint32_t b2[2] = { b[nt >> 1][nt & 1], b[nt >> 1][2 + (nt & 1)] };
                    mma_f16(acc[mt][nt], a[mt], b2);
                }
        }
    }

#pragma unroll
    for (int nt = 0; nt < 4; nt++) {
        const int n = n0 + wn + nt * 8 + 2 * t;
        const float2 bv = *reinterpret_cast<const float2*>(&bias[n]);
#pragma unroll
        for (int mt = 0; mt < 4; mt++) {
            const size_t r0 = (size_t)(m0 + wm + mt * 16 + g);
            const size_t r1 = r0 + 8;
            *reinterpret_cast<uint32_t*>(&Cout[r0 * N + n]) =
                h2u((acc[mt][nt][0] + bv.x) * scale, (acc[mt][nt][1] + bv.y) * scale);
            *reinterpret_cast<uint32_t*>(&Cout[r1 * N + n]) =
                h2u((acc[mt][nt][2] + bv.x) * scale, (acc[mt][nt][3] + bv.y) * scale);
        }
    }
}

// ---------------------------------------------------------------------------
// GEMM (NT) fp16, CTA 64x128 (output projection): halved M-tile for wave
// balance (768 CTAs vs 384 -> 1.5 effective waves instead of 2). fp32 out.
// 8 warps (2m x 4n), warp tile 32x32. Same 4-stage cp.async ring.
// ---------------------------------------------------------------------------
#define STG64_HALVES ((64 + 128) * SPH)
#define STG64_BYTES  (STG64_HALVES * 2)
#define GEMM64_SMEM_BYTES (NSTG * STG64_BYTES)

__device__ __forceinline__ void gemm64_load_stage_h(
    uint32_t sa, uint32_t sw, const __half* A, const __half* W,
    int m0, int n0, int k0, int K, int tid)
{
    // A: 64 rows x 32 halves = 256 cp16 (one per thread).
    {
        const int r  = tid >> 2;            // 0..63
        const int gg = tid & 3;             // granule 0..3 (8 halves each)
        cp16(sa + (uint32_t)((r * SPH + gg * 8) * 2),
             &A[(size_t)(m0 + r) * K + k0 + gg * 8]);
    }
    // W: 128 rows x 32 halves = 512 cp16 (two per thread).
    {
        const int r  = tid >> 1;            // 0..127
        const int g0 = (tid & 1) * 2;
#pragma unroll
        for (int j = 0; j < 2; j++) {
            const int gg = g0 + j;
            cp16(sw + (uint32_t)((r * SPH + gg * 8) * 2),
                 &W[(size_t)(n0 + r) * K + k0 + gg * 8]);
        }
    }
}

__global__ __launch_bounds__(256, 2) void gemm_f16_m64(
    const __half* __restrict__ A, const __half* __restrict__ W,
    const float* __restrict__ bias, float* __restrict__ C,
    int M, int N, int K)
{
    extern __shared__ __half smh[];
    const uint32_t base = sptr(smh);

    const int tid  = threadIdx.x;
    const int warp = tid >> 5;
    const int lane = tid & 31;
    const int g    = lane >> 2;
    const int t    = lane & 3;

    const int wm = (warp & 1) * 32;
    const int wn = (warp >> 1) * 32;
    const int m0 = blockIdx.y * 64;
    const int n0 = blockIdx.x * BN;

    const int frow = (lane & 7) + ((lane >> 3) & 1) * 8;
    const int fcol = (lane >> 4) * 8;
    uint32_t aab[2], bab[2];
#pragma unroll
    for (int mt = 0; mt < 2; mt++)
        aab[mt] = base + (uint32_t)(((wm + mt * 16 + frow) * SPH + fcol) * 2);
#pragma unroll
    for (int j = 0; j < 2; j++)
        bab[j] = base + (uint32_t)((64 * SPH + (wn + j * 16 + frow) * SPH + fcol) * 2);

    float acc[2][4][4];
#pragma unroll
    for (int i = 0; i < 2; i++)
#pragma unroll
        for (int j = 0; j < 4; j++)
#pragma unroll
            for (int c = 0; c < 4; c++) acc[i][j][c] = 0.0f;

    const int NIT = K / BKH;   // 24

#pragma unroll
    for (int s = 0; s < NSTG - 1; s++) {
        gemm64_load_stage_h(base + s * STG64_BYTES, base + s * STG64_BYTES + 64 * SPH * 2,
                            A, W, m0, n0, s * BKH, K, tid);
        asm volatile("cp.async.commit_group;\n");
    }

    for (int it = 0; it < NIT; it++) {
        asm volatile("cp.async.wait_group %0;\n" :: "n"(NSTG - 2));
        __syncthreads();

        {
            const int ld = it + NSTG - 1;
            if (ld < NIT) {
                const uint32_t so = (uint32_t)((ld % NSTG) * STG64_BYTES);
                gemm64_load_stage_h(base + so, base + so + 64 * SPH * 2,
                                    A, W, m0, n0, ld * BKH, K, tid);
            }
            asm volatile("cp.async.commit_group;\n");
        }

        const uint32_t soff = (uint32_t)((it % NSTG) * STG64_BYTES);

#pragma unroll
        for (int kc = 0; kc < 2; kc++) {
            const uint32_t koff = soff + kc * 32;
            uint32_t a[2][4], b[2][4];
#pragma unroll
            for (int mt = 0; mt < 2; mt++) ldsm4(a[mt], aab[mt] + koff);
#pragma unroll
            for (int j = 0; j < 2; j++)    ldsm4(b[j],  bab[j] + koff);
#pragma unroll
            for (int mt = 0; mt < 2; mt++)
#pragma unroll
                for (int nt = 0; nt < 4; nt++) {
                    uint32_t b2[2] = { b[nt >> 1][nt & 1], b[nt >> 1][2 + (nt & 1)] };
                    mma_f16(acc[mt][nt], a[mt], b2);
                }
        }
    }

#pragma unroll
    for (int nt = 0; nt < 4; nt++) {
        const int n = n0 + wn + nt * 8 + 2 * t;
        const float2 bv = *reinterpret_cast<const float2*>(&bias[n]);
#pragma unroll
        for (int mt = 0; mt < 2; mt++) {
            const size_t r0 = (size_t)(m0 + wm + mt * 16 + g);
            const size_t r1 = r0 + 8;
            *reinterpret_cast<float2*>(&C[r0 * N + n]) =
                make_float2(acc[mt][nt][0] + bv.x, acc[mt][nt][1] + bv.y);
            *reinterpret_cast<float2*>(&C[r1 * N + n]) =
                make_float2(acc[mt][nt][2] + bv.x, acc[mt][nt][3] + bv.y);
        }
    }
}

// ---------------------------------------------------------------------------
// Flash attention v3: all-fp16 MMA, fp32 accum. V == K.
//  - K tile = 128 keys (2 x 64-key register sub-blocks) -> half the barriers.
//  - SW128 XOR swizzle; Q fragments hoisted; P in registers; ex2 softmax.
//  - K streamed through a 3-buffer cp.async ring (wait_group 1).
// One CTA per (128 queries, head, batch). 8 warps x 16 query rows.
// ---------------------------------------------------------------------------
#define KROW 128                       // bytes per smem row (64 halves)
#define KTILE 128                      // keys per pipeline tile
#define KBUF_B (KTILE * KROW)          // 16 KB per K tile
#define ATTN_SMEM_BYTES (128 * KROW + 3 * KBUF_B)   // Q 16KB + ring 48KB

__global__ __launch_bounds__(256, 2) void attn_mma(
    const __half* __restrict__ Q, const __half* __restrict__ K,
    __half* __restrict__ O)
{
    extern __shared__ __half smh[];
    const uint32_t qbase = sptr(smh);              // Q tile [128 rows][128B], swizzled
    const uint32_t kbase0 = qbase + 128 * KROW;    // K ring: 3 x [128 rows][128B]

    const int tid  = threadIdx.x;
    const int warp = tid >> 5;
    const int lane = tid & 31;
    const int g = lane >> 2, t = lane & 3;
    const int wq = warp * 16;

    const int qt = blockIdx.x, h = blockIdx.y, b = blockIdx.z;
    const int q0 = qt * 128;

    const __half* kgm = &K[((size_t)(b * SEQ)) * EDIM + h * HD];

    // per-thread K-load mapping: 128 rows x 4 cp16 each -> 4 per thread
    const int kr  = tid >> 1;              // 0..127
    const int kg0 = (tid & 1) * 4;         // granule base 0 or 4
    const int kr7 = kr & 7;

    // ---- prologue: group0 = Q + K tile0; group1 = K tile1 ----
    {
        const int r  = tid >> 1;
        const int g0 = (tid & 1) * 4;
        const __half* src = &Q[((size_t)(b * SEQ + q0 + r)) * EDIM + h * HD + g0 * 8];
        const uint32_t drow = qbase + (uint32_t)(r * KROW);
        const int r7 = r & 7;
#pragma unroll
        for (int j = 0; j < 4; j++)
            cp16(drow + (uint32_t)(((g0 + j) ^ r7) << 4), src + j * 8);
    }
    {
        const __half* src = kgm + (size_t)kr * EDIM + kg0 * 8;
        const uint32_t drow = kbase0 + (uint32_t)(kr * KROW);
#pragma unroll
        for (int j = 0; j < 4; j++)
            cp16(drow + (uint32_t)(((kg0 + j) ^ kr7) << 4), src + j * 8);
    }
    asm volatile("cp.async.commit_group;\n");
    {
        const __half* src = kgm + (size_t)(KTILE + kr) * EDIM + kg0 * 8;
        const uint32_t drow = kbase0 + KBUF_B + (uint32_t)(kr * KROW);
#pragma unroll
        for (int j = 0; j < 4; j++)
            cp16(drow + (uint32_t)(((kg0 + j) ^ kr7) << 4), src + j * 8);
    }
    asm volatile("cp.async.commit_group;\n");

    // ---- fragment lane patterns ----
    const int frow = (lane & 7) + ((lane >> 3) & 1) * 8;   // non-trans pattern
    const int fc   = (lane >> 4);
    const int r7   = frow & 7;
    const int trow = (lane & 7) + ((lane >> 4) & 1) * 8;   // trans pattern
    const int tc   = (lane >> 3) & 1;
    const int t7   = trow & 7;

    uint32_t kbrow[4];
#pragma unroll
    for (int j = 0; j < 4; j++)
        kbrow[j] = (uint32_t)((j * 16 + frow) * KROW);
    uint32_t colp[4];
#pragma unroll
    for (int kc = 0; kc < 4; kc++)
        colp[kc] = (uint32_t)(((2 * kc + fc) ^ r7) << 4);
    uint32_t vbcol[4];
#pragma unroll
    for (int j = 0; j < 4; j++)
        vbcol[j] = (uint32_t)(((2 * j + tc) ^ t7) << 4);
    const uint32_t vtrow = (uint32_t)(trow * KROW);

    // ---- wait for Q + K0; hoist Q fragments (tile-invariant) ----
    asm volatile("cp.async.wait_group 1;\n");
    __syncthreads();
    uint32_t qf[4][4];
#pragma unroll
    for (int kc = 0; kc < 4; kc++)
        ldsm4(qf[kc], qbase + (uint32_t)((wq + frow) * KROW) + colp[kc]);

    float o[8][4];
#pragma unroll
    for (int i = 0; i < 8; i++)
#pragma unroll
        for (int j = 0; j < 4; j++) o[i][j] = 0.0f;
    float l0p = 0.0f, l1p = 0.0f;

    for (int kt = 0; kt < SEQ / KTILE; kt++) {   // 8 pipeline tiles
        asm volatile("cp.async.wait_group 1;\n");
        __syncthreads();   // K[kt] staged; all warps done with the slot being reloaded

        if (kt + 2 < SEQ / KTILE) {
            const __half* src = kgm + (size_t)((kt + 2) * KTILE + kr) * EDIM + kg0 * 8;
            const uint32_t drow = kbase0 + (uint32_t)(((kt + 2) % 3) * KBUF_B + kr * KROW);
#pragma unroll
            for (int j = 0; j < 4; j++)
                cp16(drow + (uint32_t)(((kg0 + j) ^ kr7) << 4), src + j * 8);
        }
        asm volatile("cp.async.commit_group;\n");

        const uint32_t kb = kbase0 + (uint32_t)((kt % 3) * KBUF_B);

#pragma unroll
        for (int sub = 0; sub < 2; sub++) {     // two 64-key sub-blocks
            const uint32_t sb = kb + (uint32_t)(sub * 64 * KROW);

            // ---- S = Q K^T (4 k16-chunks over d) ----
            float s[8][4];
#pragma unroll
            for (int i = 0; i < 8; i++)
#pragma unroll
                for (int j = 0; j < 4; j++) s[i][j] = 0.0f;

#pragma unroll
            for (int kc = 0; kc < 4; kc++) {
                uint32_t bb[4][4];
#pragma unroll
                for (int j = 0; j < 4; j++)
                    ldsm4(bb[j], sb + kbrow[j] + colp[kc]);
#pragma unroll
                for (int jj = 0; jj < 8; jj++) {
                    uint32_t b2[2] = { bb[jj >> 1][jj & 1], bb[jj >> 1][2 + (jj & 1)] };
                    mma_f16(s[jj], qf[kc], b2);
                }
            }

            // ---- static softmax numerator: P = 2^s ----
#pragma unroll
            for (int nt = 0; nt < 8; nt++) {
                s[nt][0] = ex2(s[nt][0]);
                s[nt][1] = ex2(s[nt][1]);
                s[nt][2] = ex2(s[nt][2]);
                s[nt][3] = ex2(s[nt][3]);
                l0p += s[nt][0] + s[nt][1];
                l1p += s[nt][2] + s[nt][3];
            }

            // ---- O += P @ V : P repacked in-register as PV A-fragments ----
#pragma unroll
            for (int kc = 0; kc < 4; kc++) {
                uint32_t pa[4];
                pa[0] = h2u(s[2 * kc][0],     s[2 * kc][1]);
                pa[1] = h2u(s[2 * kc][2],     s[2 * kc][3]);
                pa[2] = h2u(s[2 * kc + 1][0], s[2 * kc + 1][1]);
                pa[3] = h2u(s[2 * kc + 1][2], s[2 * kc + 1][3]);
                uint32_t bb[4][4];
                const uint32_t vrow = sb + (uint32_t)(kc * 16 * KROW) + vtrow;
#pragma unroll
                for (int j = 0; j < 4; j++)
                    ldsm4t(bb[j], vrow + vbcol[j]);
#pragma unroll
                for (int nd = 0; nd < 8; nd++) {
                    uint32_t b2[2] = { bb[nd >> 1][nd & 1], bb[nd >> 1][2 + (nd & 1)] };
                    mma_f16(o[nd], pa, b2);
                }
            }
        }
    }

    // ---- final row sums (quad reduce once), normalize, write fp16 O ----
#pragma unroll
    for (int off = 1; off <= 2; off <<= 1) {
        l0p += __shfl_xor_sync(0xffffffffu, l0p, off);
        l1p += __shfl_xor_sync(0xffffffffu, l1p, off);
    }
    const float inv0 = 1.0f / l0p;
    const float inv1 = 1.0f / l1p;
    const size_t row0 = (size_t)(b * SEQ + q0 + wq + g) * EDIM + h * HD;
    const size_t row1 = row0 + (size_t)8 * EDIM;
#pragma unroll
    for (int nd = 0; nd < 8; nd++) {
        const int col = nd * 8 + 2 * t;
        *reinterpret_cast<uint32_t*>(&O[row0 + col]) =
            h2u(o[nd][0] * inv0, o[nd][1] * inv0);
        *reinterpret_cast<uint32_t*>(&O[row1 + col]) =
            h2u(o[nd][2] * inv1, o[nd][3] * inv1);
    }
}

// ---------------------------------------------------------------------------
extern "C" void kernel_launch(void* const* d_in, const int* in_sizes, int n_in,
                              void* d_out, int out_size)
{
    const float* x  = (const float*)d_in[0];
    const float* Wq = (const float*)d_in[1];
    const float* bq = (const float*)d_in[2];
    const float* Wk = (const float*)d_in[3];
    const float* bk = (const float*)d_in[4];
    const float* Wo = (const float*)d_in[5];
    const float* bo = (const float*)d_in[6];
    float* out = (float*)d_out;

    __half *Xh, *Wqh, *Wkh, *Woh, *Qh, *Kh, *Oh;
    cudaGetSymbolAddress((void**)&Xh,  g_Xh);
    cudaGetSymbolAddress((void**)&Wqh, g_Wqh);
    cudaGetSymbolAddress((void**)&Wkh, g_Wkh);
    cudaGetSymbolAddress((void**)&Woh, g_Woh);
    cudaGetSymbolAddress((void**)&Qh,  g_Qh);
    cudaGetSymbolAddress((void**)&Kh,  g_Kh);
    cudaGetSymbolAddress((void**)&Oh,  g_Oh);

    cudaFuncSetAttribute(gemm_f16_bias,
                         cudaFuncAttributeMaxDynamicSharedMemorySize,
                         GEMM_SMEM_BYTES);
    cudaFuncSetAttribute(gemm_f16_m64,
                         cudaFuncAttributeMaxDynamicSharedMemorySize,
                         GEMM64_SMEM_BYTES);
    cudaFuncSetAttribute(attn_mma,
                         cudaFuncAttributeMaxDynamicSharedMemorySize,
                         ATTN_SMEM_BYTES);

    // fp16-convert all GEMM inputs in one launch.
    {
        const int total = MTOT * EDIM / 8 + 3 * (EDIM * EDIM / 8);
        cvt_half_kernel<<<(total + 255) / 256, 256>>>(x, Wq, Wk, Wo,
                                                      Xh, Wqh, Wkh, Woh);
    }

    dim3 gblk(256);

    // Q and K projections fused (grid.z selects weights); Q scale folds
    // (1/sqrt(64)) * log2(e) so attention softmax uses a bare ex2.
    dim3 gqk(EDIM / BN, MTOT / BM, 2);   // (6, 64, 2)
    gemm_f16_bias<<<gqk, gblk, GEMM_SMEM_BYTES>>>(
        Xh, Wqh, Wkh, bq, bk, Qh, Kh,
        MTOT, EDIM, EDIM, 0.125f * 1.44269504f, 1.0f);

    // Attention (V aliases K per the reference), fp16 out.
    dim3 agrid(SEQ / 128, NH, BATCH);    // (8, 12, 8)
    attn_mma<<<agrid, 256, ATTN_SMEM_BYTES>>>(Qh, Kh, Oh);

    // Output projection, fp32 out; 64-row tiles for wave balance.
    dim3 go(EDIM / BN, MTOT / 64, 1);    // (6, 128, 1)
    gemm_f16_m64<<<go, gblk, GEMM64_SMEM_BYTES>>>(
        Oh, Woh, bo, out, MTOT, EDIM, EDIM);
}

// round 17
// speedup vs baseline: 1.0733x; 1.0733x over previous
#include <cuda_runtime.h>
#include <cuda_fp16.h>
#include <cstddef>
#include <cstdint>

#define EDIM   768
#define BATCH  8
#define SEQ    1024
#define NH     12
#define HD     64
#define MTOT   (BATCH * SEQ)   // 8192

// Scratch (no cudaMalloc allowed) — fp16 dataflow.
__device__ __half g_Xh [(size_t)MTOT * EDIM];
__device__ __half g_Wqh[(size_t)EDIM * EDIM];
__device__ __half g_Wkh[(size_t)EDIM * EDIM];
__device__ __half g_Woh[(size_t)EDIM * EDIM];
__device__ __half g_Qh [(size_t)MTOT * EDIM];   // (x@Wq^T + bq) * 0.125*log2(e), fp16
__device__ __half g_Kh [(size_t)MTOT * EDIM];   // x@Wk^T + bk, fp16
__device__ __half g_Oh [(size_t)MTOT * EDIM];   // attention output, fp16

// ---------------------------------------------------------------------------
// helpers
// ---------------------------------------------------------------------------
__device__ __forceinline__ void mma_f16(float* d, const uint32_t* a, const uint32_t* b)
{
    asm volatile(
        "mma.sync.aligned.m16n8k16.row.col.f32.f16.f16.f32 "
        "{%0,%1,%2,%3}, {%4,%5,%6,%7}, {%8,%9}, {%0,%1,%2,%3};\n"
        : "+f"(d[0]), "+f"(d[1]), "+f"(d[2]), "+f"(d[3])
        : "r"(a[0]), "r"(a[1]), "r"(a[2]), "r"(a[3]),
          "r"(b[0]), "r"(b[1]));
}

__device__ __forceinline__ void ldsm4(uint32_t* r, uint32_t saddr)
{
    asm volatile(
        "ldmatrix.sync.aligned.m8n8.x4.shared.b16 {%0,%1,%2,%3}, [%4];\n"
        : "=r"(r[0]), "=r"(r[1]), "=r"(r[2]), "=r"(r[3]) : "r"(saddr));
}

__device__ __forceinline__ void ldsm4t(uint32_t* r, uint32_t saddr)
{
    asm volatile(
        "ldmatrix.sync.aligned.m8n8.x4.trans.shared.b16 {%0,%1,%2,%3}, [%4];\n"
        : "=r"(r[0]), "=r"(r[1]), "=r"(r[2]), "=r"(r[3]) : "r"(saddr));
}

__device__ __forceinline__ uint32_t sptr(const void* p)
{
    return (uint32_t)__cvta_generic_to_shared(p);
}

__device__ __forceinline__ void cp16(uint32_t s, const void* g)
{
    asm volatile("cp.async.cg.shared.global [%0], [%1], 16;\n" :: "r"(s), "l"(g));
}

__device__ __forceinline__ uint32_t h2u(float a, float b)
{
    __half2 h = __floats2half2_rn(a, b);
    return *reinterpret_cast<uint32_t*>(&h);
}

// pack (a,b) to half2 then 2^x elementwise (softmax numerator, fp16 pair).
__device__ __forceinline__ uint32_t ex2h2(float a, float b)
{
    uint32_t p = h2u(a, b);
    uint32_t r;
    asm("ex2.approx.f16x2 %0, %1;" : "=r"(r) : "r"(p));
    return r;
}

// Convert x, Wq, Wk, Wo to fp16 in one launch (8 floats per thread).
__global__ void cvt_half_kernel(
    const float* __restrict__ x,  const float* __restrict__ wq,
    const float* __restrict__ wk, const float* __restrict__ wo,
    __half* __restrict__ xo, __half* __restrict__ wqo,
    __half* __restrict__ wko, __half* __restrict__ woo)
{
    const int NX8 = MTOT * EDIM / 8;
    const int NW8 = EDIM * EDIM / 8;
    int i = blockIdx.x * blockDim.x + threadIdx.x;
    const float4* src; uint4* dst; int j;
    if (i < NX8)                { src = (const float4*)x;  dst = (uint4*)xo;  j = i; }
    else if (i < NX8 + NW8)     { src = (const float4*)wq; dst = (uint4*)wqo; j = i - NX8; }
    else if (i < NX8 + 2 * NW8) { src = (const float4*)wk; dst = (uint4*)wko; j = i - NX8 - NW8; }
    else if (i < NX8 + 3 * NW8) { src = (const float4*)wo; dst = (uint4*)woo; j = i - NX8 - 2 * NW8; }
    else return;
    float4 v0 = src[2 * j], v1 = src[2 * j + 1];
    uint4 pk;
    pk.x = h2u(v0.x, v0.y); pk.y = h2u(v0.z, v0.w);
    pk.z = h2u(v1.x, v1.y); pk.w = h2u(v1.z, v1.w);
    dst[j] = pk;
}

// ---------------------------------------------------------------------------
// GEMM (NT) fp16 m16n8k16, CTA 128x128 (R15 known-good).
// 4-stage cp.async ring + LDSM; fp32 accum. blockIdx.z selects output set.
// out_half: write __half (Q/K chain), else float (final output).
// ---------------------------------------------------------------------------
#define BM 128
#define BN 128
#define BKH 32
#define SPH 40
#define NSTG 4
#define STG_HALVES (2 * 128 * SPH)
#define STG_BYTES  (STG_HALVES * 2)
#define GEMM_SMEM_BYTES (NSTG * STG_BYTES)

__device__ __forceinline__ void gemm_load_stage_h(
    uint32_t sa, uint32_t sw, const __half* A, const __half* W,
    int m0, int n0, int k0, int K, int tid)
{
    const int r  = tid >> 1;
    const int g0 = (tid & 1) * 2;
#pragma unroll
    for (int j = 0; j < 2; j++) {
        const int gg = g0 + j;
        const uint32_t soff = (uint32_t)((r * SPH + gg * 8) * 2);
        cp16(sa + soff, &A[(size_t)(m0 + r) * K + k0 + gg * 8]);
        cp16(sw + soff, &W[(size_t)(n0 + r) * K + k0 + gg * 8]);
    }
}

__global__ __launch_bounds__(256, 2) void gemm_f16_bias(
    const __half* __restrict__ A,
    const __half* __restrict__ W0, const __half* __restrict__ W1,
    const float* __restrict__ b0, const float* __restrict__ b1,
    void* __restrict__ C0, void* __restrict__ C1,
    int M, int N, int K, float s0, float s1, int out_half)
{
    const __half* W    = blockIdx.z ? W1 : W0;
    const float*  bias = blockIdx.z ? b1 : b0;
    void*         Cout = blockIdx.z ? C1 : C0;
    const float  scale = blockIdx.z ? s1 : s0;

    extern __shared__ __half smh[];
    const uint32_t base = sptr(smh);

    const int tid  = threadIdx.x;
    const int warp = tid >> 5;
    const int lane = tid & 31;
    const int g    = lane >> 2;
    const int t    = lane & 3;

    const int wm = (warp & 1) * 64;
    const int wn = (warp >> 1) * 32;
    const int m0 = blockIdx.y * BM;
    const int n0 = blockIdx.x * BN;

    const int frow = (lane & 7) + ((lane >> 3) & 1) * 8;
    const int fcol = (lane >> 4) * 8;
    uint32_t aab[4], bab[2];
#pragma unroll
    for (int mt = 0; mt < 4; mt++)
        aab[mt] = base + (uint32_t)(((wm + mt * 16 + frow) * SPH + fcol) * 2);
#pragma unroll
    for (int j = 0; j < 2; j++)
        bab[j] = base + (uint32_t)((128 * SPH + (wn + j * 16 + frow) * SPH + fcol) * 2);

    float acc[4][4][4];
#pragma unroll
    for (int i = 0; i < 4; i++)
#pragma unroll
        for (int j = 0; j < 4; j++)
#pragma unroll
            for (int c = 0; c < 4; c++) acc[i][j][c] = 0.0f;

    const int NIT = K / BKH;   // 24

#pragma unroll
    for (int s = 0; s < NSTG - 1; s++) {
        gemm_load_stage_h(base + s * STG_BYTES, base + s * STG_BYTES + 128 * SPH * 2,
                          A, W, m0, n0, s * BKH, K, tid);
        asm volatile("cp.async.commit_group;\n");
    }

    for (int it = 0; it < NIT; it++) {
        asm volatile("cp.async.wait_group %0;\n" :: "n"(NSTG - 2));
        __syncthreads();

        {
            const int ld = it + NSTG - 1;
            if (ld < NIT) {
                const uint32_t so = (uint32_t)((ld % NSTG) * STG_BYTES);
                gemm_load_stage_h(base + so, base + so + 128 * SPH * 2,
                                  A, W, m0, n0, ld * BKH, K, tid);
            }
            asm volatile("cp.async.commit_group;\n");
        }

        const uint32_t soff = (uint32_t)((it % NSTG) * STG_BYTES);

#pragma unroll
        for (int kc = 0; kc < 2; kc++) {
            const uint32_t koff = soff + kc * 32;
            uint32_t a[4][4], b[2][4];
#pragma unroll
            for (int mt = 0; mt < 4; mt++) ldsm4(a[mt], aab[mt] + koff);
#pragma unroll
            for (int j = 0; j < 2; j++)    ldsm4(b[j],  bab[j] + koff);
#pragma unroll
            for (int mt = 0; mt < 4; mt++)
#pragma unroll
                for (int nt = 0; nt < 4; nt++) {
                    uint32_t b2[2] = { b[nt >> 1][nt & 1], b[nt >> 1][2 + (nt & 1)] };
                    mma_f16(acc[mt][nt], a[mt], b2);
                }
        }
    }

#pragma unroll
    for (int nt = 0; nt < 4; nt++) {
        const int n = n0 + wn + nt * 8 + 2 * t;
        const float2 bv = *reinterpret_cast<const float2*>(&bias[n]);
#pragma unroll
        for (int mt = 0; mt < 4; mt++) {
            const size_t r0 = (size_t)(m0 + wm + mt * 16 + g);
            const size_t r1 = r0 + 8;
            const float v00 = (acc[mt][nt][0] + bv.x) * scale;
            const float v01 = (acc[mt][nt][1] + bv.y) * scale;
            const float v10 = (acc[mt][nt][2] + bv.x) * scale;
            const float v11 = (acc[mt][nt][3] + bv.y) * scale;
            if (out_half) {
                __half* Ch = (__half*)Cout;
                *reinterpret_cast<uint32_t*>(&Ch[r0 * N + n]) = h2u(v00, v01);
                *reinterpret_cast<uint32_t*>(&Ch[r1 * N + n]) = h2u(v10, v11);
            } else {
                float* Cf = (float*)Cout;
                *reinterpret_cast<float2*>(&Cf[r0 * N + n]) = make_float2(v00, v01);
                *reinterpret_cast<float2*>(&Cf[r1 * N + n]) = make_float2(v10, v11);
            }
        }
    }
}

// ---------------------------------------------------------------------------
// Flash attention v4 (R15 structure, KTILE=64): all-fp16 MMA, fp32 accum.
//  - SW128 XOR swizzle; Q fragments hoisted; P in registers.
//  - Softmax numerator via ex2.approx.f16x2 (pack to half2 first); the
//    result IS the PV A-fragment word.
//  - Row sums via an extra ones-MMA (B = all 1.0 fp16): l lands key-reduced
//    in the accumulator; no FADDs, no shuffles.
//  - K streamed through a 3-buffer cp.async ring (wait_group 1).
// One CTA per (128 queries, head, batch). 8 warps x 16 query rows. V == K.
// ---------------------------------------------------------------------------
#define KROW 128                       // bytes per smem row (64 halves)
#define KBUF_B (64 * KROW)             // 8 KB per K tile
#define ATTN_SMEM_BYTES (128 * KROW + 3 * KBUF_B)   // Q (16KB) + K ring (24KB)

__global__ __launch_bounds__(256, 2) void attn_mma(
    const __half* __restrict__ Q, const __half* __restrict__ K,
    __half* __restrict__ O)
{
    extern __shared__ __half smh[];
    const uint32_t qbase = sptr(smh);              // Q tile [128 rows][128B], swizzled
    const uint32_t kbase0 = qbase + 128 * KROW;    // K ring: 3 x [64 rows][128B]

    const int tid  = threadIdx.x;
    const int warp = tid >> 5;
    const int lane = tid & 31;
    const int g = lane >> 2, t = lane & 3;
    const int wq = warp * 16;

    const int qt = blockIdx.x, h = blockIdx.y, b = blockIdx.z;
    const int q0 = qt * 128;

    const __half* kgm = &K[((size_t)(b * SEQ)) * EDIM + h * HD];

    // ---- prologue: cp.async Q (group with K0), then K1 ----
    {
        const int r  = tid >> 1;
        const int g0 = (tid & 1) * 4;      // granule base 0 or 4
        const __half* src = &Q[((size_t)(b * SEQ + q0 + r)) * EDIM + h * HD + g0 * 8];
        const uint32_t drow = qbase + (uint32_t)(r * KROW);
        const int r7 = r & 7;
#pragma unroll
        for (int j = 0; j < 4; j++)
            cp16(drow + (uint32_t)(((g0 + j) ^ r7) << 4), src + j * 8);
    }
    const int kr  = tid >> 2;              // 0..63
    const int kg0 = (tid & 3) * 2;         // granule base 0,2,4,6
    {
        const __half* src = kgm + (size_t)kr * EDIM + kg0 * 8;
        const uint32_t drow = kbase0 + (uint32_t)(kr * KROW);
        const int r7 = kr & 7;
        cp16(drow + (uint32_t)((kg0 ^ r7) << 4),       src);
        cp16(drow + (uint32_t)(((kg0 + 1) ^ r7) << 4), src + 8);
    }
    asm volatile("cp.async.commit_group;\n");
    {
        const __half* src = kgm + (size_t)(64 + kr) * EDIM + kg0 * 8;
        const uint32_t drow = kbase0 + KBUF_B + (uint32_t)(kr * KROW);
        const int r7 = kr & 7;
        cp16(drow + (uint32_t)((kg0 ^ r7) << 4),       src);
        cp16(drow + (uint32_t)(((kg0 + 1) ^ r7) << 4), src + 8);
    }
    asm volatile("cp.async.commit_group;\n");

    // ---- fragment lane patterns ----
    const int frow = (lane & 7) + ((lane >> 3) & 1) * 8;   // non-trans pattern
    const int fc   = (lane >> 4);                          // granule low bit (0/1)
    const int r7   = frow & 7;
    const int trow = (lane & 7) + ((lane >> 4) & 1) * 8;   // trans pattern
    const int tc   = (lane >> 3) & 1;
    const int t7   = trow & 7;

    uint32_t kbrow[4];
#pragma unroll
    for (int j = 0; j < 4; j++)
        kbrow[j] = (uint32_t)((j * 16 + frow) * KROW);
    uint32_t colp[4];
#pragma unroll
    for (int kc = 0; kc < 4; kc++)
        colp[kc] = (uint32_t)(((2 * kc + fc) ^ r7) << 4);
    uint32_t vbcol[4];
#pragma unroll
    for (int j = 0; j < 4; j++)
        vbcol[j] = (uint32_t)(((2 * j + tc) ^ t7) << 4);
    const uint32_t vtrow = (uint32_t)(trow * KROW);

    // ---- wait for Q + K0; hoist Q fragments (tile-invariant) ----
    asm volatile("cp.async.wait_group 1;\n");
    __syncthreads();
    uint32_t qf[4][4];
#pragma unroll
    for (int kc = 0; kc < 4; kc++)
        ldsm4(qf[kc], qbase + (uint32_t)((wq + frow) * KROW) + colp[kc]);

    float o[8][4];
#pragma unroll
    for (int i = 0; i < 8; i++)
#pragma unroll
        for (int j = 0; j < 4; j++) o[i][j] = 0.0f;
    float lacc[4] = {0.0f, 0.0f, 0.0f, 0.0f};   // row sums via ones-MMA
    const uint32_t ones2[2] = {0x3C003C00u, 0x3C003C00u};

    for (int kt = 0; kt < SEQ / 64; kt++) {
        asm volatile("cp.async.wait_group 1;\n");
        __syncthreads();   // K[kt] staged; all warps done with the slot being reloaded

        if (kt + 2 < SEQ / 64) {
            const __half* src = kgm + (size_t)((kt + 2) * 64 + kr) * EDIM + kg0 * 8;
            const uint32_t drow = kbase0 + (uint32_t)(((kt + 2) % 3) * KBUF_B + kr * KROW);
            const int kr7 = kr & 7;
            cp16(drow + (uint32_t)((kg0 ^ kr7) << 4),       src);
            cp16(drow + (uint32_t)(((kg0 + 1) ^ kr7) << 4), src + 8);
        }
        asm volatile("cp.async.commit_group;\n");

        const uint32_t kb = kbase0 + (uint32_t)((kt % 3) * KBUF_B);

        // ---- S = Q K^T (4 k16-chunks over d) ----
        float s[8][4];
#pragma unroll
        for (int i = 0; i < 8; i++)
#pragma unroll
            for (int j = 0; j < 4; j++) s[i][j] = 0.0f;

#pragma unroll
        for (int kc = 0; kc < 4; kc++) {
            uint32_t bb[4][4];
#pragma unroll
            for (int j = 0; j < 4; j++)
                ldsm4(bb[j], kb + kbrow[j] + colp[kc]);
#pragma unroll
            for (int jj = 0; jj < 8; jj++) {
                uint32_t b2[2] = { bb[jj >> 1][jj & 1], bb[jj >> 1][2 + (jj & 1)] };
                mma_f16(s[jj], qf[kc], b2);
            }
        }

        // ---- P = 2^s directly in fp16 pairs (PV A-fragments) ----
        uint32_t paf[4][4];
#pragma unroll
        for (int kc = 0; kc < 4; kc++) {
            paf[kc][0] = ex2h2(s[2 * kc][0],     s[2 * kc][1]);
            paf[kc][1] = ex2h2(s[2 * kc][2],     s[2 * kc][3]);
            paf[kc][2] = ex2h2(s[2 * kc + 1][0], s[2 * kc + 1][1]);
            paf[kc][3] = ex2h2(s[2 * kc + 1][2], s[2 * kc + 1][3]);
        }

        // ---- row sums: l += P @ ones (key-reduced in accumulator) ----
#pragma unroll
        for (int kc = 0; kc < 4; kc++)
            mma_f16(lacc, paf[kc], ones2);

        // ---- O += P @ V (V = K tile; B-op = trans-LDSM of [key][d]) ----
#pragma unroll
        for (int kc = 0; kc < 4; kc++) {
            uint32_t bb[4][4];
            const uint32_t vrow = kb + (uint32_t)(kc * 16 * KROW) + vtrow;
#pragma unroll
            for (int j = 0; j < 4; j++)
                ldsm4t(bb[j], vrow + vbcol[j]);
#pragma unroll
            for (int nd = 0; nd < 8; nd++) {
                uint32_t b2[2] = { bb[nd >> 1][nd & 1], bb[nd >> 1][2 + (nd & 1)] };
                mma_f16(o[nd], paf[kc], b2);
            }
        }
    }

    // ---- normalize (l already reduced across keys), write fp16 O ----
    const float inv0 = 1.0f / lacc[0];
    const float inv1 = 1.0f / lacc[2];
    const size_t row0 = (size_t)(b * SEQ + q0 + wq + g) * EDIM + h * HD;
    const size_t row1 = row0 + (size_t)8 * EDIM;
#pragma unroll
    for (int nd = 0; nd < 8; nd++) {
        const int col = nd * 8 + 2 * t;
        *reinterpret_cast<uint32_t*>(&O[row0 + col]) =
            h2u(o[nd][0] * inv0, o[nd][1] * inv0);
        *reinterpret_cast<uint32_t*>(&O[row1 + col]) =
            h2u(o[nd][2] * inv1, o[nd][3] * inv1);
    }
}

// ---------------------------------------------------------------------------
extern "C" void kernel_launch(void* const* d_in, const int* in_sizes, int n_in,
                              void* d_out, int out_size)
{
    const float* x  = (const float*)d_in[0];
    const float* Wq = (const float*)d_in[1];
    const float* bq = (const float*)d_in[2];
    const float* Wk = (const float*)d_in[3];
    const float* bk = (const float*)d_in[4];
    const float* Wo = (const float*)d_in[5];
    const float* bo = (const float*)d_in[6];
    float* out = (float*)d_out;

    __half *Xh, *Wqh, *Wkh, *Woh, *Qh, *Kh, *Oh;
    cudaGetSymbolAddress((void**)&Xh,  g_Xh);
    cudaGetSymbolAddress((void**)&Wqh, g_Wqh);
    cudaGetSymbolAddress((void**)&Wkh, g_Wkh);
    cudaGetSymbolAddress((void**)&Woh, g_Woh);
    cudaGetSymbolAddress((void**)&Qh,  g_Qh);
    cudaGetSymbolAddress((void**)&Kh,  g_Kh);
    cudaGetSymbolAddress((void**)&Oh,  g_Oh);

    cudaFuncSetAttribute(gemm_f16_bias,
                         cudaFuncAttributeMaxDynamicSharedMemorySize,
                         GEMM_SMEM_BYTES);
    cudaFuncSetAttribute(attn_mma,
                         cudaFuncAttributeMaxDynamicSharedMemorySize,
                         ATTN_SMEM_BYTES);

    // fp16-convert all GEMM inputs in one launch.
    {
        const int total = MTOT * EDIM / 8 + 3 * (EDIM * EDIM / 8);
        cvt_half_kernel<<<(total + 255) / 256, 256>>>(x, Wq, Wk, Wo,
                                                      Xh, Wqh, Wkh, Woh);
    }

    dim3 gblk(256);

    // Q and K projections fused (grid.z selects weights); Q scale folds
    // (1/sqrt(64)) * log2(e) so attention softmax uses a bare ex2.
    dim3 gqk(EDIM / BN, MTOT / BM, 2);   // (6, 64, 2)
    gemm_f16_bias<<<gqk, gblk, GEMM_SMEM_BYTES>>>(
        Xh, Wqh, Wkh, bq, bk, (void*)Qh, (void*)Kh,
        MTOT, EDIM, EDIM, 0.125f * 1.44269504f, 1.0f, 1);

    // Attention (V aliases K per the reference), fp16 out.
    dim3 agrid(SEQ / 128, NH, BATCH);    // (8, 12, 8)
    attn_mma<<<agrid, 256, ATTN_SMEM_BYTES>>>(Qh, Kh, Oh);

    // Output projection, fp32 out (R15 known-good 128x128 GEMM).
    dim3 go(EDIM / BN, MTOT / BM, 1);    // (6, 64, 1)
    gemm_f16_bias<<<go, gblk, GEMM_SMEM_BYTES>>>(
        Oh, Woh, Woh, bo, bo, (void*)out, (void*)out,
        MTOT, EDIM, EDIM, 1.0f, 1.0f, 0);
}